// round 3
// baseline (speedup 1.0000x reference)
#include <cuda_runtime.h>
#include <math.h>

#define Bq 2
#define Tt 1024
#define DM 512
#define Hh 8
#define DEP 64
#define NTOK (Bq*Tt)      // 2048
#define BH   (Bq*Hh)      // 16
#define NBHT (BH*Tt)      // 16384

// ---------------- scratch (device globals; no allocation) ----------------
__device__ float g_Q[NTOK*DM];
__device__ float g_K[NTOK*DM];
__device__ float g_V[NTOK*DM];
__device__ float g_Cb[NTOK*DM];
__device__ float g_wphi[128];
__device__ float g_wtau[128];
__device__ float g_cphi[1];
__device__ float g_ctau[1];
__device__ float g_pq_phi[NBHT], g_pk_phi[NBHT];
__device__ float g_pq_ta [NBHT], g_pk_ta [NBHT];
__device__ float g_pq_tb [NBHT], g_pk_tb [NBHT];
__device__ float g_pq_tau[NBHT], g_pk_tau[NBHT];

// ---------------- 1. collapse the linear-linear per-pair MLPs ----------------
__global__ void combine_kernel(const float* __restrict__ Wpi, const float* __restrict__ bpi,
                               const float* __restrict__ Wpo, const float* __restrict__ bpo,
                               const float* __restrict__ Wti, const float* __restrict__ bti,
                               const float* __restrict__ Wto, const float* __restrict__ bto) {
    int i = threadIdx.x;  // 128 threads
    float s = 0.f;
    for (int m = 0; m < 512; m++) s += Wpi[i*512 + m] * Wpo[m];
    g_wphi[i] = s;
    float s2 = 0.f;
    for (int m = 0; m < 256; m++) s2 += Wti[i*256 + m] * Wto[m];
    g_wtau[i] = s2;
    if (i == 0) {
        float c = bpo[0];
        for (int m = 0; m < 512; m++) c += bpi[m] * Wpo[m];
        g_cphi[0] = c;
        float c2 = bto[0];
        for (int m = 0; m < 256; m++) c2 += bti[m] * Wto[m];
        g_ctau[0] = c2;
    }
}

// ---------------- 2. GEMM: C[2048,512] = A[2048,512] @ W[512,512] + bias ----------------
// 128x64 tile, BK=16, 256 threads, 8x4 per thread. z-mux over 3 weight sets.
__global__ void __launch_bounds__(256, 3)
gemm_bias3(const float* __restrict__ A,
           const float* __restrict__ W0, const float* __restrict__ b0, float* __restrict__ C0,
           const float* __restrict__ W1, const float* __restrict__ b1, float* __restrict__ C1,
           const float* __restrict__ W2, const float* __restrict__ b2, float* __restrict__ C2) {
    __shared__ float As[16][132];
    __shared__ float Ws[16][68];
    const int tid = threadIdx.x;
    const int tx = tid & 15, ty = tid >> 4;
    const int m0 = blockIdx.y * 128, n0 = blockIdx.x * 64;
    const int z = blockIdx.z;
    const float* W  = (z == 0) ? W0 : (z == 1) ? W1 : W2;
    const float* bi = (z == 0) ? b0 : (z == 1) ? b1 : b2;
    float*       C  = (z == 0) ? C0 : (z == 1) ? C1 : C2;

    const int ar   = tid >> 1;
    const int ah   = (tid & 1) * 8;
    const int wkk  = tid >> 4;
    const int wn   = (tid & 15) * 4;

    float acc[8][4] = {};
    for (int k0 = 0; k0 < 512; k0 += 16) {
        const float* ap = A + (size_t)(m0 + ar) * 512 + k0 + ah;
        float4 a0 = *(const float4*)(ap);
        float4 a1 = *(const float4*)(ap + 4);
        As[ah + 0][ar] = a0.x; As[ah + 1][ar] = a0.y;
        As[ah + 2][ar] = a0.z; As[ah + 3][ar] = a0.w;
        As[ah + 4][ar] = a1.x; As[ah + 5][ar] = a1.y;
        As[ah + 6][ar] = a1.z; As[ah + 7][ar] = a1.w;
        *(float4*)&Ws[wkk][wn] = *(const float4*)(W + (size_t)(k0 + wkk) * 512 + n0 + wn);
        __syncthreads();
        #pragma unroll
        for (int kk = 0; kk < 16; kk++) {
            float a[8], w[4];
            *(float4*)(a)     = *(float4*)&As[kk][ty*8];
            *(float4*)(a + 4) = *(float4*)&As[kk][ty*8 + 4];
            *(float4*)(w)     = *(float4*)&Ws[kk][tx*4];
            #pragma unroll
            for (int i = 0; i < 8; i++)
                #pragma unroll
                for (int j = 0; j < 4; j++)
                    acc[i][j] += a[i] * w[j];
        }
        __syncthreads();
    }
    float4 bv = *(const float4*)(bi + n0 + tx*4);
    #pragma unroll
    for (int i = 0; i < 8; i++) {
        float4 o;
        o.x = acc[i][0] + bv.x; o.y = acc[i][1] + bv.y;
        o.z = acc[i][2] + bv.z; o.w = acc[i][3] + bv.w;
        *(float4*)(C + (size_t)(m0 + ty*8 + i) * 512 + n0 + tx*4) = o;
    }
}

// ---------------- 3. per-token feature scalars (one warp per (b,h,t)) ----------------
__global__ void token_kernel(const float* __restrict__ Wta, const float* __restrict__ bta,
                             const float* __restrict__ Wtb, const float* __restrict__ btb) {
    int gw   = (blockIdx.x * blockDim.x + threadIdx.x) >> 5;
    int lane = threadIdx.x & 31;
    if (gw >= NBHT) return;
    int bh = gw >> 10, t = gw & 1023;
    int b = bh >> 3, h = bh & 7;
    size_t base = ((size_t)(b*Tt + t))*DM + h*DEP;
    float q0 = g_Q[base+lane], q1 = g_Q[base+lane+32];
    float k0 = g_K[base+lane], k1 = g_K[base+lane+32];

    float sphiq = q0*g_wphi[lane]    + q1*g_wphi[lane+32];
    float sphik = k0*g_wphi[64+lane] + k1*g_wphi[96+lane];
    float staq  = q0*Wta[lane]       + q1*Wta[lane+32];
    float stak  = k0*Wta[64+lane]    + k1*Wta[96+lane];
    float stbq  = q0*Wtb[lane]       + q1*Wtb[lane+32];
    float stbk  = k0*Wtb[64+lane]    + k1*Wtb[96+lane];
    float stauq = q0*g_wtau[lane]    + q1*g_wtau[lane+32];
    float stauk = k0*g_wtau[64+lane] + k1*g_wtau[96+lane];

    #pragma unroll
    for (int off = 16; off; off >>= 1) {
        sphiq += __shfl_xor_sync(0xffffffffu, sphiq, off);
        sphik += __shfl_xor_sync(0xffffffffu, sphik, off);
        staq  += __shfl_xor_sync(0xffffffffu, staq,  off);
        stak  += __shfl_xor_sync(0xffffffffu, stak,  off);
        stbq  += __shfl_xor_sync(0xffffffffu, stbq,  off);
        stbk  += __shfl_xor_sync(0xffffffffu, stbk,  off);
        stauq += __shfl_xor_sync(0xffffffffu, stauq, off);
        stauk += __shfl_xor_sync(0xffffffffu, stauk, off);
    }
    if (lane == 0) {
        g_pq_phi[gw] = sphiq + g_cphi[0];
        g_pk_phi[gw] = sphik;
        g_pq_ta [gw] = staq + bta[0];
        g_pk_ta [gw] = stak;
        g_pq_tb [gw] = stbq + btb[0];
        g_pk_tb [gw] = stbk;
        g_pq_tau[gw] = stauq + g_ctau[0];
        g_pk_tau[gw] = stauk;
    }
}

// ---------------- 4. FUSED: scores + online top-16 + logits + softmax + V-gather ----------------
// grid (8 q-tiles, 16 bh), 512 threads. Never materializes the TxT score matrix.
#define FSM_FLOATS (64*132*2 + 128*132 + 128*17*2)

__global__ void __launch_bounds__(512, 1) fused_attn() {
    extern __shared__ float sm[];
    float* Qs   = sm;                        // [64][132]  d-major
    float* Ks   = Qs + 64*132;               // [64][132]
    float* Ss   = Ks + 64*132;               // [128][132] score staging
    float* topv = Ss + 128*132;              // [128][17]
    int*   topi = (int*)(topv + 128*17);     // [128][17]

    const int tid = threadIdx.x;
    const int tx = tid & 15, ty = tid >> 4;  // ty 0..31 -> 4 q-rows; tx -> 8 j-cols
    const int bh = blockIdx.y, b = bh >> 3, h = bh & 7;
    const int q0 = blockIdx.x * 128;

    for (int i = tid; i < 128*17; i += 512) { topv[i] = -INFINITY; topi[i] = 0; }

    // load Q tile once: Qs[d][r]
    {
        const int r = tid >> 2, ds = (tid & 3) * 16;
        const float* qp = g_Q + (size_t)(b*Tt + q0 + r)*DM + h*DEP + ds;
        #pragma unroll
        for (int u = 0; u < 4; u++) {
            float4 v = *(const float4*)(qp + u*4);
            int d = ds + u*4;
            Qs[(d+0)*132 + r] = v.x; Qs[(d+1)*132 + r] = v.y;
            Qs[(d+2)*132 + r] = v.z; Qs[(d+3)*132 + r] = v.w;
        }
    }

    for (int jt = 0; jt < 8; jt++) {
        // load K tile: Ks[d][r]
        {
            const int r = tid >> 2, ds = (tid & 3) * 16;
            const float* kp = g_K + (size_t)(b*Tt + jt*128 + r)*DM + h*DEP + ds;
            #pragma unroll
            for (int u = 0; u < 4; u++) {
                float4 v = *(const float4*)(kp + u*4);
                int d = ds + u*4;
                Ks[(d+0)*132 + r] = v.x; Ks[(d+1)*132 + r] = v.y;
                Ks[(d+2)*132 + r] = v.z; Ks[(d+3)*132 + r] = v.w;
            }
        }
        __syncthreads();

        float acc[4][8] = {};
        #pragma unroll
        for (int d = 0; d < 64; d++) {
            float a[4], w[8];
            *(float4*)(a)     = *(float4*)&Qs[d*132 + ty*4];
            *(float4*)(w)     = *(float4*)&Ks[d*132 + tx*8];
            *(float4*)(w + 4) = *(float4*)&Ks[d*132 + tx*8 + 4];
            #pragma unroll
            for (int i = 0; i < 4; i++)
                #pragma unroll
                for (int j = 0; j < 8; j++)
                    acc[i][j] += a[i] * w[j];
        }
        // stage this 128x128 score tile
        #pragma unroll
        for (int i = 0; i < 4; i++) {
            *(float4*)&Ss[(ty*4+i)*132 + tx*8]     = make_float4(acc[i][0], acc[i][1], acc[i][2], acc[i][3]);
            *(float4*)&Ss[(ty*4+i)*132 + tx*8 + 4] = make_float4(acc[i][4], acc[i][5], acc[i][6], acc[i][7]);
        }
        __syncthreads();

        // 128 row-owners merge into running top-16 (threshold filtered)
        if (tid < 128) {
            const int row = tid;
            float* tv = topv + row*17;
            int*   ti = topi + row*17;
            float thr = tv[15];
            const int jbase = jt * 128;
            #pragma unroll 4
            for (int k4 = 0; k4 < 32; k4++) {
                float4 v = *(float4*)&Ss[row*132 + k4*4];
                float m4 = fmaxf(fmaxf(v.x, v.y), fmaxf(v.z, v.w));
                if (m4 > thr) {
                    float vv[4] = {v.x, v.y, v.z, v.w};
                    #pragma unroll
                    for (int c = 0; c < 4; c++) {
                        float val = vv[c];
                        if (val > thr) {
                            int p = 15;
                            while (p > 0 && tv[p-1] < val) p--;   // equals stay above -> lowest index wins
                            for (int s2 = 15; s2 > p; s2--) { tv[s2] = tv[s2-1]; ti[s2] = ti[s2-1]; }
                            tv[p] = val; ti[p] = jbase + k4*4 + c;
                            thr = tv[15];
                        }
                    }
                }
            }
        }
        __syncthreads();
    }

    // logits + softmax per query row
    if (tid < 128) {
        const int row = tid, q = q0 + row, pqi = bh*1024 + q;
        const float pq_phi = g_pq_phi[pqi], pq_ta = g_pq_ta[pqi];
        const float pq_tb  = g_pq_tb[pqi],  pq_tau = g_pq_tau[pqi];
        float* tv = topv + row*17;
        int*   ti = topi + row*17;
        float lg[16];
        float mx = -INFINITY;
        #pragma unroll
        for (int l = 0; l < 16; l++) {
            int pki = bh*1024 + ti[l];
            float phi = 1.f / (1.f + expf(-(pq_phi + g_pk_phi[pki])));
            float tiv = 1.f / (1.f + expf(-((pq_ta + g_pk_ta[pki]) + (pq_tb + g_pk_tb[pki]))));
            float xt  = pq_tau + g_pk_tau[pki];
            float sp  = (xt > 20.f) ? xt : log1pf(expf(xt));
            float tau = sp + 1e-6f;
            float L = phi / tau * (1.f - expf(-tau * tiv));
            lg[l] = L; mx = fmaxf(mx, L);
        }
        float ssum = 0.f;
        #pragma unroll
        for (int l = 0; l < 16; l++) { lg[l] = expf(lg[l] - mx); ssum += lg[l]; }
        float inv = 1.f / ssum;
        #pragma unroll
        for (int l = 0; l < 16; l++) tv[l] = lg[l] * inv;   // overwrite vals with weights
    }
    __syncthreads();

    // V gather: 4 threads per row, 16 d each
    {
        const int row = tid >> 2, ds = (tid & 3) * 16;
        const float* tv = topv + row*17;
        const int*   ti = topi + row*17;
        float4 a0 = {0,0,0,0}, a1 = a0, a2 = a0, a3 = a0;
        #pragma unroll
        for (int l = 0; l < 16; l++) {
            float a = tv[l]; int j = ti[l];
            const float4* vp = (const float4*)(g_V + (size_t)(b*Tt + j)*DM + h*DEP + ds);
            float4 v0 = vp[0], v1 = vp[1], v2 = vp[2], v3 = vp[3];
            a0.x += a*v0.x; a0.y += a*v0.y; a0.z += a*v0.z; a0.w += a*v0.w;
            a1.x += a*v1.x; a1.y += a*v1.y; a1.z += a*v1.z; a1.w += a*v1.w;
            a2.x += a*v2.x; a2.y += a*v2.y; a2.z += a*v2.z; a2.w += a*v2.w;
            a3.x += a*v3.x; a3.y += a*v3.y; a3.z += a*v3.z; a3.w += a*v3.w;
        }
        float* op = g_Cb + (size_t)(b*Tt + q0 + row)*DM + h*DEP + ds;
        *(float4*)(op)      = a0;
        *(float4*)(op + 4)  = a1;
        *(float4*)(op + 8)  = a2;
        *(float4*)(op + 12) = a3;
    }
}

// ---------------- launch ----------------
extern "C" void kernel_launch(void* const* d_in, const int* in_sizes, int n_in,
                              void* d_out, int out_size) {
    const float* x   = (const float*)d_in[0];
    const float* Wq  = (const float*)d_in[1];
    const float* bq  = (const float*)d_in[2];
    const float* Wk  = (const float*)d_in[3];
    const float* bk  = (const float*)d_in[4];
    const float* Wv  = (const float*)d_in[5];
    const float* bv  = (const float*)d_in[6];
    const float* Wo  = (const float*)d_in[7];
    const float* bo  = (const float*)d_in[8];
    const float* Wpi = (const float*)d_in[9];
    const float* bpi = (const float*)d_in[10];
    const float* Wpo = (const float*)d_in[11];
    const float* bpo = (const float*)d_in[12];
    const float* Wta = (const float*)d_in[13];
    const float* bta = (const float*)d_in[14];
    const float* Wtb = (const float*)d_in[15];
    const float* btb = (const float*)d_in[16];
    const float* Wti = (const float*)d_in[17];
    const float* bti = (const float*)d_in[18];
    const float* Wto = (const float*)d_in[19];
    const float* bto = (const float*)d_in[20];

    float *Qp, *Kp, *Vp, *Cbp;
    cudaGetSymbolAddress((void**)&Qp,  g_Q);
    cudaGetSymbolAddress((void**)&Kp,  g_K);
    cudaGetSymbolAddress((void**)&Vp,  g_V);
    cudaGetSymbolAddress((void**)&Cbp, g_Cb);

    const int fsm_bytes = FSM_FLOATS * 4;
    cudaFuncSetAttribute(fused_attn, cudaFuncAttributeMaxDynamicSharedMemorySize, fsm_bytes);

    combine_kernel<<<1, 128>>>(Wpi, bpi, Wpo, bpo, Wti, bti, Wto, bto);

    gemm_bias3<<<dim3(8, 16, 3), 256>>>(x, Wq, bq, Qp, Wk, bk, Kp, Wv, bv, Vp);

    token_kernel<<<NBHT/8, 256>>>(Wta, bta, Wtb, btb);

    fused_attn<<<dim3(8, 16), 512, fsm_bytes>>>();

    gemm_bias3<<<dim3(8, 16, 1), 256>>>(Cbp, Wo, bo, (float*)d_out,
                                        Wo, bo, (float*)d_out, Wo, bo, (float*)d_out);
}

// round 4
// speedup vs baseline: 2.6594x; 2.6594x over previous
#include <cuda_runtime.h>
#include <math.h>

#define Bq 2
#define Tt 1024
#define DM 512
#define Hh 8
#define DEP 64
#define NTOK (Bq*Tt)      // 2048
#define BH   (Bq*Hh)      // 16
#define NBHT (BH*Tt)      // 16384

// ---------------- scratch (device globals; no allocation) ----------------
__device__ float g_Q[NTOK*DM];
__device__ float g_K[NTOK*DM];
__device__ float g_V[NTOK*DM];
__device__ float g_Cb[NTOK*DM];
__device__ float g_S[(size_t)BH*Tt*Tt];   // 64 MB scores
__device__ float g_wphi[128];
__device__ float g_wtau[128];
__device__ float g_cphi[1];
__device__ float g_ctau[1];
__device__ float g_pq_phi[NBHT], g_pk_phi[NBHT];
__device__ float g_pq_ta [NBHT], g_pk_ta [NBHT];
__device__ float g_pq_tb [NBHT], g_pk_tb [NBHT];
__device__ float g_pq_tau[NBHT], g_pk_tau[NBHT];

// ---------------- 1. collapse the linear-linear per-pair MLPs (warp per output) ----------------
__global__ void combine_kernel(const float* __restrict__ Wpi, const float* __restrict__ bpi,
                               const float* __restrict__ Wpo, const float* __restrict__ bpo,
                               const float* __restrict__ Wti, const float* __restrict__ bti,
                               const float* __restrict__ Wto, const float* __restrict__ bto) {
    const unsigned FULL = 0xffffffffu;
    int w    = (blockIdx.x * blockDim.x + threadIdx.x) >> 5;   // 0..159
    int lane = threadIdx.x & 31;
    if (w < 128) {
        float s = 0.f;
        for (int m = lane; m < 512; m += 32) s += Wpi[w*512 + m] * Wpo[m];
        float s2 = 0.f;
        for (int m = lane; m < 256; m += 32) s2 += Wti[w*256 + m] * Wto[m];
        #pragma unroll
        for (int off = 16; off; off >>= 1) {
            s  += __shfl_xor_sync(FULL, s,  off);
            s2 += __shfl_xor_sync(FULL, s2, off);
        }
        if (lane == 0) { g_wphi[w] = s; g_wtau[w] = s2; }
    } else if (w == 128) {
        float c = 0.f;
        for (int m = lane; m < 512; m += 32) c += bpi[m] * Wpo[m];
        #pragma unroll
        for (int off = 16; off; off >>= 1) c += __shfl_xor_sync(FULL, c, off);
        if (lane == 0) g_cphi[0] = c + bpo[0];
    } else if (w == 129) {
        float c2 = 0.f;
        for (int m = lane; m < 256; m += 32) c2 += bti[m] * Wto[m];
        #pragma unroll
        for (int off = 16; off; off >>= 1) c2 += __shfl_xor_sync(FULL, c2, off);
        if (lane == 0) g_ctau[0] = c2 + bto[0];
    }
}

// ---------------- 2. GEMM: C[2048,512] = A[2048,512] @ W[512,512] + bias ----------------
// 128x64 tile, BK=16, 256 threads, 8x4 per thread. z-mux over 3 weight sets.
__global__ void __launch_bounds__(256, 3)
gemm_bias3(const float* __restrict__ A,
           const float* __restrict__ W0, const float* __restrict__ b0, float* __restrict__ C0,
           const float* __restrict__ W1, const float* __restrict__ b1, float* __restrict__ C1,
           const float* __restrict__ W2, const float* __restrict__ b2, float* __restrict__ C2) {
    __shared__ float As[16][132];
    __shared__ float Ws[16][68];
    const int tid = threadIdx.x;
    const int tx = tid & 15, ty = tid >> 4;
    const int m0 = blockIdx.y * 128, n0 = blockIdx.x * 64;
    const int z = blockIdx.z;
    const float* W  = (z == 0) ? W0 : (z == 1) ? W1 : W2;
    const float* bi = (z == 0) ? b0 : (z == 1) ? b1 : b2;
    float*       C  = (z == 0) ? C0 : (z == 1) ? C1 : C2;

    const int ar   = tid >> 1;
    const int ah   = (tid & 1) * 8;
    const int wkk  = tid >> 4;
    const int wn   = (tid & 15) * 4;

    float acc[8][4] = {};
    for (int k0 = 0; k0 < 512; k0 += 16) {
        const float* ap = A + (size_t)(m0 + ar) * 512 + k0 + ah;
        float4 a0 = *(const float4*)(ap);
        float4 a1 = *(const float4*)(ap + 4);
        As[ah + 0][ar] = a0.x; As[ah + 1][ar] = a0.y;
        As[ah + 2][ar] = a0.z; As[ah + 3][ar] = a0.w;
        As[ah + 4][ar] = a1.x; As[ah + 5][ar] = a1.y;
        As[ah + 6][ar] = a1.z; As[ah + 7][ar] = a1.w;
        *(float4*)&Ws[wkk][wn] = *(const float4*)(W + (size_t)(k0 + wkk) * 512 + n0 + wn);
        __syncthreads();
        #pragma unroll
        for (int kk = 0; kk < 16; kk++) {
            float a[8], w[4];
            *(float4*)(a)     = *(float4*)&As[kk][ty*8];
            *(float4*)(a + 4) = *(float4*)&As[kk][ty*8 + 4];
            *(float4*)(w)     = *(float4*)&Ws[kk][tx*4];
            #pragma unroll
            for (int i = 0; i < 8; i++)
                #pragma unroll
                for (int j = 0; j < 4; j++)
                    acc[i][j] += a[i] * w[j];
        }
        __syncthreads();
    }
    float4 bv = *(const float4*)(bi + n0 + tx*4);
    #pragma unroll
    for (int i = 0; i < 8; i++) {
        float4 o;
        o.x = acc[i][0] + bv.x; o.y = acc[i][1] + bv.y;
        o.z = acc[i][2] + bv.z; o.w = acc[i][3] + bv.w;
        *(float4*)(C + (size_t)(m0 + ty*8 + i) * 512 + n0 + tx*4) = o;
    }
}

// ---------------- 3. per-token feature scalars (one warp per (b,h,t)) ----------------
__global__ void token_kernel(const float* __restrict__ Wta, const float* __restrict__ bta,
                             const float* __restrict__ Wtb, const float* __restrict__ btb) {
    int gw   = (blockIdx.x * blockDim.x + threadIdx.x) >> 5;
    int lane = threadIdx.x & 31;
    if (gw >= NBHT) return;
    int bh = gw >> 10, t = gw & 1023;
    int b = bh >> 3, h = bh & 7;
    size_t base = ((size_t)(b*Tt + t))*DM + h*DEP;
    float q0 = g_Q[base+lane], q1 = g_Q[base+lane+32];
    float k0 = g_K[base+lane], k1 = g_K[base+lane+32];

    float sphiq = q0*g_wphi[lane]    + q1*g_wphi[lane+32];
    float sphik = k0*g_wphi[64+lane] + k1*g_wphi[96+lane];
    float staq  = q0*Wta[lane]       + q1*Wta[lane+32];
    float stak  = k0*Wta[64+lane]    + k1*Wta[96+lane];
    float stbq  = q0*Wtb[lane]       + q1*Wtb[lane+32];
    float stbk  = k0*Wtb[64+lane]    + k1*Wtb[96+lane];
    float stauq = q0*g_wtau[lane]    + q1*g_wtau[lane+32];
    float stauk = k0*g_wtau[64+lane] + k1*g_wtau[96+lane];

    #pragma unroll
    for (int off = 16; off; off >>= 1) {
        sphiq += __shfl_xor_sync(0xffffffffu, sphiq, off);
        sphik += __shfl_xor_sync(0xffffffffu, sphik, off);
        staq  += __shfl_xor_sync(0xffffffffu, staq,  off);
        stak  += __shfl_xor_sync(0xffffffffu, stak,  off);
        stbq  += __shfl_xor_sync(0xffffffffu, stbq,  off);
        stbk  += __shfl_xor_sync(0xffffffffu, stbk,  off);
        stauq += __shfl_xor_sync(0xffffffffu, stauq, off);
        stauk += __shfl_xor_sync(0xffffffffu, stauk, off);
    }
    if (lane == 0) {
        g_pq_phi[gw] = sphiq + g_cphi[0];
        g_pk_phi[gw] = sphik;
        g_pq_ta [gw] = staq + bta[0];
        g_pk_ta [gw] = stak;
        g_pq_tb [gw] = stbq + btb[0];
        g_pk_tb [gw] = stbk;
        g_pq_tau[gw] = stauq + g_ctau[0];
        g_pk_tau[gw] = stauk;
    }
}

// ---------------- 4. scores S[bh,q,j] = q_h . k_h  (128x128 tile, 8x8/thread) ----------------
__global__ void __launch_bounds__(256, 2) scores_kernel() {
    __shared__ float Qs[32][132];
    __shared__ float Ks[32][132];
    const int tid = threadIdx.x;
    const int tx = tid & 15, ty = tid >> 4;
    const int bh = blockIdx.z;
    const int b = bh >> 3, h = bh & 7;
    const int j0 = blockIdx.x * 128, q0 = blockIdx.y * 128;
    const int r = tid >> 1, half = (tid & 1) * 16;

    float acc[8][8] = {};
    #pragma unroll
    for (int c = 0; c < 2; c++) {
        const int d0 = c * 32;
        const float* qp = g_Q + ((size_t)(b*Tt + q0 + r))*DM + h*DEP + d0 + half;
        const float* kp = g_K + ((size_t)(b*Tt + j0 + r))*DM + h*DEP + d0 + half;
        #pragma unroll
        for (int u = 0; u < 4; u++) {
            float4 qv = *(const float4*)(qp + u*4);
            float4 kv = *(const float4*)(kp + u*4);
            int d = half + u*4;
            Qs[d+0][r] = qv.x; Qs[d+1][r] = qv.y; Qs[d+2][r] = qv.z; Qs[d+3][r] = qv.w;
            Ks[d+0][r] = kv.x; Ks[d+1][r] = kv.y; Ks[d+2][r] = kv.z; Ks[d+3][r] = kv.w;
        }
        __syncthreads();
        #pragma unroll
        for (int d = 0; d < 32; d++) {
            float a[8], w[8];
            *(float4*)(a)     = *(float4*)&Qs[d][ty*8];
            *(float4*)(a + 4) = *(float4*)&Qs[d][ty*8 + 4];
            *(float4*)(w)     = *(float4*)&Ks[d][tx*8];
            *(float4*)(w + 4) = *(float4*)&Ks[d][tx*8 + 4];
            #pragma unroll
            for (int i = 0; i < 8; i++)
                #pragma unroll
                for (int j = 0; j < 8; j++)
                    acc[i][j] += a[i] * w[j];
        }
        __syncthreads();
    }
    #pragma unroll
    for (int i = 0; i < 8; i++) {
        float* out = g_S + ((size_t)bh*Tt + q0 + ty*8 + i)*Tt + j0 + tx*8;
        *(float4*)(out)     = make_float4(acc[i][0], acc[i][1], acc[i][2], acc[i][3]);
        *(float4*)(out + 4) = make_float4(acc[i][4], acc[i][5], acc[i][6], acc[i][7]);
    }
}

// ---------------- 5. top-16 via segment-max tournament + REDUX argmax ----------------
// monotone float->uint order map
__device__ __forceinline__ unsigned fmap(float f) {
    unsigned b = __float_as_uint(f);
    return b ^ (((unsigned)((int)b >> 31)) | 0x80000000u);
}

__global__ void attn_kernel() {
    __shared__ float sc[8][1056];    // per-warp 32 classes x 33 stride
    const unsigned FULL = 0xffffffffu;
    int warp = threadIdx.x >> 5, lane = threadIdx.x & 31;
    int wq = blockIdx.x * 8 + warp;
    int bh = wq >> 10, q = wq & 1023;
    int b = bh >> 3, h = bh & 7;

    const float* srow = g_S + ((size_t)bh*Tt + q)*Tt;
    float* s = sc[warp];
    // load + bank-swizzled scatter: value at index i lives at (i&31)*33 + (i>>5)
    #pragma unroll
    for (int u = 0; u < 8; u++) {
        int i = u*128 + lane*4;
        float4 v = *(const float4*)(srow + i);
        int hi = i >> 5;                      // same for all 4 (i aligned to 4, <32 span)
        s[((i+0)&31)*33 + hi] = v.x;
        s[((i+1)&31)*33 + hi] = v.y;
        s[((i+2)&31)*33 + hi] = v.z;
        s[((i+3)&31)*33 + hi] = v.w;
    }
    __syncwarp();

    // per-lane class max: class=lane holds indices {u*32+lane}
    float segv = -INFINITY; int segu = 0;
    #pragma unroll
    for (int u = 0; u < 32; u++) {
        float v = s[lane*33 + u];
        if (v > segv) { segv = v; segu = u; }   // ascending u, strict >  -> smallest index on ties
    }

    int jsel = 0;
    #pragma unroll 1
    for (int r = 0; r < 16; r++) {
        // global argmax via REDUX: value order by fmap, ties -> min index
        unsigned uv = fmap(segv);
        unsigned mx = __reduce_max_sync(FULL, uv);
        int jcand = (uv == mx) ? (segu*32 + lane) : 0x7fffffff;
        int bj = (int)__reduce_min_sync(FULL, (unsigned)jcand);
        if (lane == r) jsel = bj;
        int wr = bj & 31, wu = bj >> 5;
        if (lane == wu) s[wr*33 + wu] = -INFINITY;   // zap
        __syncwarp();
        // cooperative rescan of class wr
        float v = s[wr*33 + lane];
        unsigned uv2 = fmap(v);
        unsigned mx2 = __reduce_max_sync(FULL, uv2);
        int ucand = (uv2 == mx2) ? lane : 32;
        int nu = (int)__reduce_min_sync(FULL, (unsigned)ucand);
        float nv = __shfl_sync(FULL, v, nu);
        if (lane == wr) { segv = nv; segu = nu; }
        __syncwarp();
    }

    // logits for the 16 selected keys (lanes 0..15)
    float logit = -INFINITY;
    int pqi = bh*1024 + q;
    if (lane < 16) {
        int pki = bh*1024 + jsel;
        float aphi = g_pq_phi[pqi] + g_pk_phi[pki];
        float phi  = 1.f / (1.f + expf(-aphi));
        float ta   = g_pq_ta[pqi]  + g_pk_ta[pki];
        float tb   = g_pq_tb[pqi]  + g_pk_tb[pki];
        float ti   = 1.f / (1.f + expf(-(ta + tb)));      // t_scalar = 1
        float xt   = g_pq_tau[pqi] + g_pk_tau[pki];
        float sp   = (xt > 20.f) ? xt : log1pf(expf(xt)); // softplus
        float tau  = sp + 1e-6f;
        logit = phi / tau * (1.f - expf(-tau * ti));
    }
    float m = logit;
    #pragma unroll
    for (int off = 16; off; off >>= 1) m = fmaxf(m, __shfl_xor_sync(FULL, m, off));
    float e = (lane < 16) ? expf(logit - m) : 0.f;
    float ssum = e;
    #pragma unroll
    for (int off = 16; off; off >>= 1) ssum += __shfl_xor_sync(FULL, ssum, off);
    float aw = e / ssum;

    // out[d] = sum_l attn_l * V[j_l][d]
    float acc0 = 0.f, acc1 = 0.f;
    #pragma unroll
    for (int l = 0; l < 16; l++) {
        float a = __shfl_sync(FULL, aw,   l);
        int   j = __shfl_sync(FULL, jsel, l);
        const float* vp = g_V + ((size_t)(b*Tt + j))*DM + h*DEP;
        acc0 += a * vp[lane];
        acc1 += a * vp[lane+32];
    }
    float* op = g_Cb + ((size_t)(b*Tt + q))*DM + h*DEP;
    op[lane]    = acc0;   // DT = 1
    op[lane+32] = acc1;
}

// ---------------- launch ----------------
extern "C" void kernel_launch(void* const* d_in, const int* in_sizes, int n_in,
                              void* d_out, int out_size) {
    const float* x   = (const float*)d_in[0];
    const float* Wq  = (const float*)d_in[1];
    const float* bq  = (const float*)d_in[2];
    const float* Wk  = (const float*)d_in[3];
    const float* bk  = (const float*)d_in[4];
    const float* Wv  = (const float*)d_in[5];
    const float* bv  = (const float*)d_in[6];
    const float* Wo  = (const float*)d_in[7];
    const float* bo  = (const float*)d_in[8];
    const float* Wpi = (const float*)d_in[9];
    const float* bpi = (const float*)d_in[10];
    const float* Wpo = (const float*)d_in[11];
    const float* bpo = (const float*)d_in[12];
    const float* Wta = (const float*)d_in[13];
    const float* bta = (const float*)d_in[14];
    const float* Wtb = (const float*)d_in[15];
    const float* btb = (const float*)d_in[16];
    const float* Wti = (const float*)d_in[17];
    const float* bti = (const float*)d_in[18];
    const float* Wto = (const float*)d_in[19];
    const float* bto = (const float*)d_in[20];

    float *Qp, *Kp, *Vp, *Cbp;
    cudaGetSymbolAddress((void**)&Qp,  g_Q);
    cudaGetSymbolAddress((void**)&Kp,  g_K);
    cudaGetSymbolAddress((void**)&Vp,  g_V);
    cudaGetSymbolAddress((void**)&Cbp, g_Cb);

    combine_kernel<<<5, 1024>>>(Wpi, bpi, Wpo, bpo, Wti, bti, Wto, bto);

    gemm_bias3<<<dim3(8, 16, 3), 256>>>(x, Wq, bq, Qp, Wk, bk, Kp, Wv, bv, Vp);

    token_kernel<<<NBHT/8, 256>>>(Wta, bta, Wtb, btb);

    scores_kernel<<<dim3(8, 8, 16), 256>>>();

    attn_kernel<<<NBHT/8, 256>>>();

    gemm_bias3<<<dim3(8, 16, 1), 256>>>(Cbp, Wo, bo, (float*)d_out,
                                        Wo, bo, (float*)d_out, Wo, bo, (float*)d_out);
}

// round 5
// speedup vs baseline: 2.7055x; 1.0173x over previous
#include <cuda_runtime.h>
#include <math.h>

#define Bq 2
#define Tt 1024
#define DM 512
#define Hh 8
#define DEP 64
#define NTOK (Bq*Tt)      // 2048
#define BH   (Bq*Hh)      // 16
#define NBHT (BH*Tt)      // 16384

// ---------------- packed fp32x2 FMA helpers (Blackwell FFMA2) ----------------
__device__ __forceinline__ void ffma2(unsigned long long &acc, unsigned long long a,
                                      unsigned long long b) {
    asm("fma.rn.f32x2 %0, %1, %2, %0;" : "+l"(acc) : "l"(a), "l"(b));
}
__device__ __forceinline__ unsigned long long pack2(float x, float y) {
    unsigned long long r;
    asm("mov.b64 %0, {%1, %2};" : "=l"(r) : "f"(x), "f"(y));
    return r;
}
__device__ __forceinline__ void unpack2(unsigned long long v, float &x, float &y) {
    asm("mov.b64 {%0, %1}, %2;" : "=f"(x), "=f"(y) : "l"(v));
}

// ---------------- scratch (device globals; no allocation) ----------------
__device__ float g_Q[NTOK*DM];
__device__ float g_K[NTOK*DM];
__device__ float g_V[NTOK*DM];
__device__ float g_Cb[NTOK*DM];
__device__ float g_S[(size_t)BH*Tt*Tt];   // 64 MB scores
__device__ float g_wphi[128];
__device__ float g_wtau[128];
__device__ float g_cphi[1];
__device__ float g_ctau[1];
__device__ float g_pq_phi[NBHT], g_pk_phi[NBHT];
__device__ float g_pq_ta [NBHT], g_pk_ta [NBHT];
__device__ float g_pq_tb [NBHT], g_pk_tb [NBHT];
__device__ float g_pq_tau[NBHT], g_pk_tau[NBHT];

// ---------------- 1. collapse the linear-linear per-pair MLPs (warp per output) ----------------
__global__ void combine_kernel(const float* __restrict__ Wpi, const float* __restrict__ bpi,
                               const float* __restrict__ Wpo, const float* __restrict__ bpo,
                               const float* __restrict__ Wti, const float* __restrict__ bti,
                               const float* __restrict__ Wto, const float* __restrict__ bto) {
    const unsigned FULL = 0xffffffffu;
    int w    = (blockIdx.x * blockDim.x + threadIdx.x) >> 5;   // 0..159
    int lane = threadIdx.x & 31;
    if (w < 128) {
        float s = 0.f;
        for (int m = lane; m < 512; m += 32) s += Wpi[w*512 + m] * Wpo[m];
        float s2 = 0.f;
        for (int m = lane; m < 256; m += 32) s2 += Wti[w*256 + m] * Wto[m];
        #pragma unroll
        for (int off = 16; off; off >>= 1) {
            s  += __shfl_xor_sync(FULL, s,  off);
            s2 += __shfl_xor_sync(FULL, s2, off);
        }
        if (lane == 0) { g_wphi[w] = s; g_wtau[w] = s2; }
    } else if (w == 128) {
        float c = 0.f;
        for (int m = lane; m < 512; m += 32) c += bpi[m] * Wpo[m];
        #pragma unroll
        for (int off = 16; off; off >>= 1) c += __shfl_xor_sync(FULL, c, off);
        if (lane == 0) g_cphi[0] = c + bpo[0];
    } else if (w == 129) {
        float c2 = 0.f;
        for (int m = lane; m < 256; m += 32) c2 += bti[m] * Wto[m];
        #pragma unroll
        for (int off = 16; off; off >>= 1) c2 += __shfl_xor_sync(FULL, c2, off);
        if (lane == 0) g_ctau[0] = c2 + bto[0];
    }
}

// ---------------- 2. GEMM: C[2048,512] = A[2048,512] @ W[512,512] + bias ----------------
// 128x64 tile, BK=16, 256 threads, 8x4 per thread (FFMA2: m-pairs). z-mux over 3 weight sets.
__global__ void __launch_bounds__(256, 3)
gemm_bias3(const float* __restrict__ A,
           const float* __restrict__ W0, const float* __restrict__ b0, float* __restrict__ C0,
           const float* __restrict__ W1, const float* __restrict__ b1, float* __restrict__ C1,
           const float* __restrict__ W2, const float* __restrict__ b2, float* __restrict__ C2) {
    __shared__ float As[16][132];
    __shared__ float Ws[16][68];
    const int tid = threadIdx.x;
    const int tx = tid & 15, ty = tid >> 4;
    const int m0 = blockIdx.y * 128, n0 = blockIdx.x * 64;
    const int z = blockIdx.z;
    const float* W  = (z == 0) ? W0 : (z == 1) ? W1 : W2;
    const float* bi = (z == 0) ? b0 : (z == 1) ? b1 : b2;
    float*       C  = (z == 0) ? C0 : (z == 1) ? C1 : C2;

    const int ar   = tid >> 1;
    const int ah   = (tid & 1) * 8;
    const int wkk  = tid >> 4;
    const int wn   = (tid & 15) * 4;

    unsigned long long accp[4][4] = {};   // m-pairs (rows 2ip,2ip+1) x 4 n
    for (int k0 = 0; k0 < 512; k0 += 16) {
        const float* ap2 = A + (size_t)(m0 + ar) * 512 + k0 + ah;
        float4 a0 = *(const float4*)(ap2);
        float4 a1 = *(const float4*)(ap2 + 4);
        As[ah + 0][ar] = a0.x; As[ah + 1][ar] = a0.y;
        As[ah + 2][ar] = a0.z; As[ah + 3][ar] = a0.w;
        As[ah + 4][ar] = a1.x; As[ah + 5][ar] = a1.y;
        As[ah + 6][ar] = a1.z; As[ah + 7][ar] = a1.w;
        *(float4*)&Ws[wkk][wn] = *(const float4*)(W + (size_t)(k0 + wkk) * 512 + n0 + wn);
        __syncthreads();
        #pragma unroll
        for (int kk = 0; kk < 16; kk++) {
            float a[8], w[4];
            *(float4*)(a)     = *(float4*)&As[kk][ty*8];
            *(float4*)(a + 4) = *(float4*)&As[kk][ty*8 + 4];
            *(float4*)(w)     = *(float4*)&Ws[kk][tx*4];
            unsigned long long ap[4], wd[4];
            #pragma unroll
            for (int ip = 0; ip < 4; ip++) ap[ip] = pack2(a[2*ip], a[2*ip+1]);
            #pragma unroll
            for (int j = 0; j < 4; j++) wd[j] = pack2(w[j], w[j]);
            #pragma unroll
            for (int ip = 0; ip < 4; ip++)
                #pragma unroll
                for (int j = 0; j < 4; j++)
                    ffma2(accp[ip][j], ap[ip], wd[j]);
        }
        __syncthreads();
    }
    float4 bv = *(const float4*)(bi + n0 + tx*4);
    #pragma unroll
    for (int ip = 0; ip < 4; ip++) {
        float r0[4], r1[4];
        #pragma unroll
        for (int j = 0; j < 4; j++) unpack2(accp[ip][j], r0[j], r1[j]);
        float4 o0, o1;
        o0.x = r0[0] + bv.x; o0.y = r0[1] + bv.y; o0.z = r0[2] + bv.z; o0.w = r0[3] + bv.w;
        o1.x = r1[0] + bv.x; o1.y = r1[1] + bv.y; o1.z = r1[2] + bv.z; o1.w = r1[3] + bv.w;
        *(float4*)(C + (size_t)(m0 + ty*8 + 2*ip)     * 512 + n0 + tx*4) = o0;
        *(float4*)(C + (size_t)(m0 + ty*8 + 2*ip + 1) * 512 + n0 + tx*4) = o1;
    }
}

// ---------------- 3. per-token feature scalars (one warp per (b,h,t)) ----------------
__global__ void token_kernel(const float* __restrict__ Wta, const float* __restrict__ bta,
                             const float* __restrict__ Wtb, const float* __restrict__ btb) {
    int gw   = (blockIdx.x * blockDim.x + threadIdx.x) >> 5;
    int lane = threadIdx.x & 31;
    if (gw >= NBHT) return;
    int bh = gw >> 10, t = gw & 1023;
    int b = bh >> 3, h = bh & 7;
    size_t base = ((size_t)(b*Tt + t))*DM + h*DEP;
    float q0 = g_Q[base+lane], q1 = g_Q[base+lane+32];
    float k0 = g_K[base+lane], k1 = g_K[base+lane+32];

    float sphiq = q0*g_wphi[lane]    + q1*g_wphi[lane+32];
    float sphik = k0*g_wphi[64+lane] + k1*g_wphi[96+lane];
    float staq  = q0*Wta[lane]       + q1*Wta[lane+32];
    float stak  = k0*Wta[64+lane]    + k1*Wta[96+lane];
    float stbq  = q0*Wtb[lane]       + q1*Wtb[lane+32];
    float stbk  = k0*Wtb[64+lane]    + k1*Wtb[96+lane];
    float stauq = q0*g_wtau[lane]    + q1*g_wtau[lane+32];
    float stauk = k0*g_wtau[64+lane] + k1*g_wtau[96+lane];

    #pragma unroll
    for (int off = 16; off; off >>= 1) {
        sphiq += __shfl_xor_sync(0xffffffffu, sphiq, off);
        sphik += __shfl_xor_sync(0xffffffffu, sphik, off);
        staq  += __shfl_xor_sync(0xffffffffu, staq,  off);
        stak  += __shfl_xor_sync(0xffffffffu, stak,  off);
        stbq  += __shfl_xor_sync(0xffffffffu, stbq,  off);
        stbk  += __shfl_xor_sync(0xffffffffu, stbk,  off);
        stauq += __shfl_xor_sync(0xffffffffu, stauq, off);
        stauk += __shfl_xor_sync(0xffffffffu, stauk, off);
    }
    if (lane == 0) {
        g_pq_phi[gw] = sphiq + g_cphi[0];
        g_pk_phi[gw] = sphik;
        g_pq_ta [gw] = staq + bta[0];
        g_pk_ta [gw] = stak;
        g_pq_tb [gw] = stbq + btb[0];
        g_pk_tb [gw] = stbk;
        g_pq_tau[gw] = stauq + g_ctau[0];
        g_pk_tau[gw] = stauk;
    }
}

// ---------------- 4. scores S[bh,q,j] = q_h . k_h  (128x128 tile, FFMA2 m-pairs) ----------------
__global__ void __launch_bounds__(256, 2) scores_kernel() {
    __shared__ float Qs[32][132];
    __shared__ float Ks[32][132];
    const int tid = threadIdx.x;
    const int tx = tid & 15, ty = tid >> 4;
    const int bh = blockIdx.z;
    const int b = bh >> 3, h = bh & 7;
    const int j0 = blockIdx.x * 128, q0 = blockIdx.y * 128;
    const int r = tid >> 1, half = (tid & 1) * 16;

    unsigned long long accp[4][8] = {};   // q-pairs x 8 j
    #pragma unroll
    for (int c = 0; c < 2; c++) {
        const int d0 = c * 32;
        const float* qp = g_Q + ((size_t)(b*Tt + q0 + r))*DM + h*DEP + d0 + half;
        const float* kp = g_K + ((size_t)(b*Tt + j0 + r))*DM + h*DEP + d0 + half;
        #pragma unroll
        for (int u = 0; u < 4; u++) {
            float4 qv = *(const float4*)(qp + u*4);
            float4 kv = *(const float4*)(kp + u*4);
            int d = half + u*4;
            Qs[d+0][r] = qv.x; Qs[d+1][r] = qv.y; Qs[d+2][r] = qv.z; Qs[d+3][r] = qv.w;
            Ks[d+0][r] = kv.x; Ks[d+1][r] = kv.y; Ks[d+2][r] = kv.z; Ks[d+3][r] = kv.w;
        }
        __syncthreads();
        #pragma unroll
        for (int d = 0; d < 32; d++) {
            float a[8], w[8];
            *(float4*)(a)     = *(float4*)&Qs[d][ty*8];
            *(float4*)(a + 4) = *(float4*)&Qs[d][ty*8 + 4];
            *(float4*)(w)     = *(float4*)&Ks[d][tx*8];
            *(float4*)(w + 4) = *(float4*)&Ks[d][tx*8 + 4];
            unsigned long long ap[4], wd[8];
            #pragma unroll
            for (int ip = 0; ip < 4; ip++) ap[ip] = pack2(a[2*ip], a[2*ip+1]);
            #pragma unroll
            for (int j = 0; j < 8; j++) wd[j] = pack2(w[j], w[j]);
            #pragma unroll
            for (int ip = 0; ip < 4; ip++)
                #pragma unroll
                for (int j = 0; j < 8; j++)
                    ffma2(accp[ip][j], ap[ip], wd[j]);
        }
        __syncthreads();
    }
    #pragma unroll
    for (int ip = 0; ip < 4; ip++) {
        float r0[8], r1[8];
        #pragma unroll
        for (int j = 0; j < 8; j++) unpack2(accp[ip][j], r0[j], r1[j]);
        float* out0 = g_S + ((size_t)bh*Tt + q0 + ty*8 + 2*ip)*Tt + j0 + tx*8;
        float* out1 = out0 + Tt;
        *(float4*)(out0)     = make_float4(r0[0], r0[1], r0[2], r0[3]);
        *(float4*)(out0 + 4) = make_float4(r0[4], r0[5], r0[6], r0[7]);
        *(float4*)(out1)     = make_float4(r1[0], r1[1], r1[2], r1[3]);
        *(float4*)(out1 + 4) = make_float4(r1[4], r1[5], r1[6], r1[7]);
    }
}

// ---------------- 5. top-16 via segment-max tournament + REDUX argmax ----------------
__device__ __forceinline__ unsigned fmap(float f) {
    unsigned b = __float_as_uint(f);
    return b ^ (((unsigned)((int)b >> 31)) | 0x80000000u);
}

__global__ void attn_kernel() {
    __shared__ float sc[8][1056];    // per-warp 32 classes x 33 stride
    const unsigned FULL = 0xffffffffu;
    int warp = threadIdx.x >> 5, lane = threadIdx.x & 31;
    int wq = blockIdx.x * 8 + warp;
    int bh = wq >> 10, q = wq & 1023;
    int b = bh >> 3, h = bh & 7;

    const float* srow = g_S + ((size_t)bh*Tt + q)*Tt;
    float* s = sc[warp];
    #pragma unroll
    for (int u = 0; u < 8; u++) {
        int i = u*128 + lane*4;
        float4 v = *(const float4*)(srow + i);
        int hi = i >> 5;
        s[((i+0)&31)*33 + hi] = v.x;
        s[((i+1)&31)*33 + hi] = v.y;
        s[((i+2)&31)*33 + hi] = v.z;
        s[((i+3)&31)*33 + hi] = v.w;
    }
    __syncwarp();

    float segv = -INFINITY; int segu = 0;
    #pragma unroll
    for (int u = 0; u < 32; u++) {
        float v = s[lane*33 + u];
        if (v > segv) { segv = v; segu = u; }
    }

    int jsel = 0;
    #pragma unroll 1
    for (int r = 0; r < 16; r++) {
        unsigned uv = fmap(segv);
        unsigned mx = __reduce_max_sync(FULL, uv);
        int jcand = (uv == mx) ? (segu*32 + lane) : 0x7fffffff;
        int bj = (int)__reduce_min_sync(FULL, (unsigned)jcand);
        if (lane == r) jsel = bj;
        int wr = bj & 31, wu = bj >> 5;
        if (lane == wu) s[wr*33 + wu] = -INFINITY;
        __syncwarp();
        float v = s[wr*33 + lane];
        unsigned uv2 = fmap(v);
        unsigned mx2 = __reduce_max_sync(FULL, uv2);
        int ucand = (uv2 == mx2) ? lane : 32;
        int nu = (int)__reduce_min_sync(FULL, (unsigned)ucand);
        float nv = __shfl_sync(FULL, v, nu);
        if (lane == wr) { segv = nv; segu = nu; }
        __syncwarp();
    }

    float logit = -INFINITY;
    int pqi = bh*1024 + q;
    if (lane < 16) {
        int pki = bh*1024 + jsel;
        float aphi = g_pq_phi[pqi] + g_pk_phi[pki];
        float phi  = 1.f / (1.f + expf(-aphi));
        float ta   = g_pq_ta[pqi]  + g_pk_ta[pki];
        float tb   = g_pq_tb[pqi]  + g_pk_tb[pki];
        float ti   = 1.f / (1.f + expf(-(ta + tb)));
        float xt   = g_pq_tau[pqi] + g_pk_tau[pki];
        float sp   = (xt > 20.f) ? xt : log1pf(expf(xt));
        float tau  = sp + 1e-6f;
        logit = phi / tau * (1.f - expf(-tau * ti));
    }
    float m = logit;
    #pragma unroll
    for (int off = 16; off; off >>= 1) m = fmaxf(m, __shfl_xor_sync(FULL, m, off));
    float e = (lane < 16) ? expf(logit - m) : 0.f;
    float ssum = e;
    #pragma unroll
    for (int off = 16; off; off >>= 1) ssum += __shfl_xor_sync(FULL, ssum, off);
    float aw = e / ssum;

    float acc0 = 0.f, acc1 = 0.f;
    #pragma unroll
    for (int l = 0; l < 16; l++) {
        float a = __shfl_sync(FULL, aw,   l);
        int   j = __shfl_sync(FULL, jsel, l);
        const float* vp = g_V + ((size_t)(b*Tt + j))*DM + h*DEP;
        acc0 += a * vp[lane];
        acc1 += a * vp[lane+32];
    }
    float* op = g_Cb + ((size_t)(b*Tt + q))*DM + h*DEP;
    op[lane]    = acc0;
    op[lane+32] = acc1;
}

// ---------------- launch ----------------
extern "C" void kernel_launch(void* const* d_in, const int* in_sizes, int n_in,
                              void* d_out, int out_size) {
    const float* x   = (const float*)d_in[0];
    const float* Wq  = (const float*)d_in[1];
    const float* bq  = (const float*)d_in[2];
    const float* Wk  = (const float*)d_in[3];
    const float* bk  = (const float*)d_in[4];
    const float* Wv  = (const float*)d_in[5];
    const float* bv  = (const float*)d_in[6];
    const float* Wo  = (const float*)d_in[7];
    const float* bo  = (const float*)d_in[8];
    const float* Wpi = (const float*)d_in[9];
    const float* bpi = (const float*)d_in[10];
    const float* Wpo = (const float*)d_in[11];
    const float* bpo = (const float*)d_in[12];
    const float* Wta = (const float*)d_in[13];
    const float* bta = (const float*)d_in[14];
    const float* Wtb = (const float*)d_in[15];
    const float* btb = (const float*)d_in[16];
    const float* Wti = (const float*)d_in[17];
    const float* bti = (const float*)d_in[18];
    const float* Wto = (const float*)d_in[19];
    const float* bto = (const float*)d_in[20];

    float *Qp, *Kp, *Vp, *Cbp;
    cudaGetSymbolAddress((void**)&Qp,  g_Q);
    cudaGetSymbolAddress((void**)&Kp,  g_K);
    cudaGetSymbolAddress((void**)&Vp,  g_V);
    cudaGetSymbolAddress((void**)&Cbp, g_Cb);

    combine_kernel<<<5, 1024>>>(Wpi, bpi, Wpo, bpo, Wti, bti, Wto, bto);

    gemm_bias3<<<dim3(8, 16, 3), 256>>>(x, Wq, bq, Qp, Wk, bk, Kp, Wv, bv, Vp);

    token_kernel<<<NBHT/8, 256>>>(Wta, bta, Wtb, btb);

    scores_kernel<<<dim3(8, 8, 16), 256>>>();

    attn_kernel<<<NBHT/8, 256>>>();

    gemm_bias3<<<dim3(8, 16, 1), 256>>>(Cbp, Wo, bo, (float*)d_out,
                                        Wo, bo, (float*)d_out, Wo, bo, (float*)d_out);
}